// round 12
// baseline (speedup 1.0000x reference)
#include <cuda_runtime.h>
#include <math.h>

#define NEG_INF (-1e10f)
#define BATCH 4
#define NN 1024
#define DD 32
#define WPR 32   // u32 words per bitset row
#define FULL 0xFFFFFFFFu

#define PACK_BLOCKS (BATCH * NN / 8)        // 512, warp per row
#define GMAX_BLOCKS (BATCH * 32 / 8)        // 16,  warp per (b,group)

// 512KB bitset scratch + 16KB group-max scratch (device globals: allowed)
__device__ unsigned g_bits[BATCH * NN * WPR];
__device__ float    g_gm[BATCH * 32 * DD];   // [b][group][d]

// ---------------------------------------------------------------------------
// Fused: pack edges -> bitset rows (blocks [0,512)) + group maxes (blocks
// [512,528)). Pack: one warp per row, uint4 loads front-batched (MLP=8),
// shfl-OR reduce. launch_bounds(256,2): 128-reg budget for the load batch.
// ---------------------------------------------------------------------------
__global__ __launch_bounds__(256, 2)
void pack_gmax_kernel(const int* __restrict__ edges,
                      const float* __restrict__ feat) {
    const int lane = threadIdx.x & 31;
    const int warp = threadIdx.x >> 5;

    if (blockIdx.x < PACK_BLOCKS) {
        const int rowId = blockIdx.x * 8 + warp;            // 0..4095
        const uint4* row = (const uint4*)(edges + (size_t)rowId * NN);
        // Front-batch all 8 uint4 loads.
        uint4 v[8];
        #pragma unroll
        for (int i = 0; i < 8; ++i) v[i] = row[i * 32 + lane];

        unsigned myword = 0u;
        #pragma unroll
        for (int i = 0; i < 8; ++i) {
            unsigned nib = (unsigned)(v[i].x != 0)
                         | ((unsigned)(v[i].y != 0) << 1)
                         | ((unsigned)(v[i].z != 0) << 2)
                         | ((unsigned)(v[i].w != 0) << 3);
            unsigned val = nib << ((lane & 7) * 4);
            // OR-butterfly within each 8-lane group -> word (i*4 + lane>>3)
            val |= __shfl_xor_sync(FULL, val, 1);
            val |= __shfl_xor_sync(FULL, val, 2);
            val |= __shfl_xor_sync(FULL, val, 4);
            // lane 4i+g grabs word g of this iteration (held by lane g*8)
            unsigned w = __shfl_sync(FULL, val, (lane & 3) << 3);
            if ((lane >> 2) == i) myword = w;
        }
        g_bits[rowId * WPR + lane] = myword;                // coalesced
    } else {
        // group maxes: warp per (b,group); idx = b*32+g in [0,128)
        const int idx = (blockIdx.x - PACK_BLOCKS) * 8 + warp;
        const float* f = feat + (size_t)idx * 32 * DD + lane;
        float m0 = f[0], m1 = f[DD], m2 = f[2 * DD], m3 = f[3 * DD];
        #pragma unroll
        for (int j = 4; j < 32; j += 4) {
            m0 = fmaxf(m0, f[j * DD]);
            m1 = fmaxf(m1, f[(j + 1) * DD]);
            m2 = fmaxf(m2, f[(j + 2) * DD]);
            m3 = fmaxf(m3, f[(j + 3) * DD]);
        }
        g_gm[idx * DD + lane] = fmaxf(fmaxf(m0, m1), fmaxf(m2, m3));
    }
}

// ---------------------------------------------------------------------------
// E2-row construction: per round, load ALL 32 rows of word-group w with
// compile-time addresses (no shfl-gather, no fns, fully unconditional ->
// ptxas front-batches the LDGs) and mask each with (0 - bit) before ORing.
// No smem, no __syncthreads -> pure independent warps; launch_bounds(256,4)
// gives 4 blocks/SM so all 512 blocks run in ONE wave.
// Exact saturation early-exit; exact general pooling fallback (L2 reads).
// Grid: (NN/8, BATCH), 256 threads, one warp per output row.
// ---------------------------------------------------------------------------
__global__ __launch_bounds__(256, 4)
void pool_kernel(const float* __restrict__ feat, float* __restrict__ out) {
    const int b    = blockIdx.y;
    const int lane = threadIdx.x & 31;
    const int warp = threadIdx.x >> 5;
    const int i    = blockIdx.x * 8 + warp;        // output row

    const unsigned* __restrict__ bb = g_bits + (size_t)b * NN * WPR;
    const float*    __restrict__ gm = g_gm + b * 32 * DD;
    const float*    __restrict__ fb = feat + (size_t)b * NN * DD;

    const unsigned rw = bb[i * WPR + lane];        // row i of E (L2)

    // --- build E2 row i: acc (lane holds word `lane`) ---
    unsigned acc = 0u;
    bool sat = false;                              // warp-uniform
    #pragma unroll 1
    for (int w = 0; w < 32 && !sat; ++w) {
        const unsigned m = __shfl_sync(FULL, rw, w);   // warp-uniform word
        if (!m) continue;
        // Rows (w*32+t), t=0..31: base pointer for this word-group.
        const unsigned* __restrict__ gp = bb + ((size_t)w << 10) + lane;

        unsigned v0 = 0u, v1 = 0u, v2 = 0u, v3 = 0u;
        unsigned v4 = 0u, v5 = 0u, v6 = 0u, v7 = 0u;
        #pragma unroll
        for (int t = 0; t < 32; t += 8) {
            v0 |= gp[(t    ) << 5] & (0u - ((m >> (t    )) & 1u));
            v1 |= gp[(t + 1) << 5] & (0u - ((m >> (t + 1)) & 1u));
            v2 |= gp[(t + 2) << 5] & (0u - ((m >> (t + 2)) & 1u));
            v3 |= gp[(t + 3) << 5] & (0u - ((m >> (t + 3)) & 1u));
            v4 |= gp[(t + 4) << 5] & (0u - ((m >> (t + 4)) & 1u));
            v5 |= gp[(t + 5) << 5] & (0u - ((m >> (t + 5)) & 1u));
            v6 |= gp[(t + 6) << 5] & (0u - ((m >> (t + 6)) & 1u));
            v7 |= gp[(t + 7) << 5] & (0u - ((m >> (t + 7)) & 1u));
        }
        acc |= ((v0 | v1) | (v2 | v3)) | ((v4 | v5) | (v6 | v7));
        // Exact: once all 1024 bits set, further ORs are no-ops.
        sat = __all_sync(FULL, acc == FULL);
    }

    float best;
    if (sat) {
        // Everything visible: max over all group maxes (L1-resident 4KB).
        best = gm[lane];
        #pragma unroll
        for (int g = 1; g < 32; ++g) best = fmaxf(best, gm[(g << 5) + lane]);
    } else {
        best = -INFINITY;
        #pragma unroll 1
        for (int g = 0; g < 32; ++g) {
            const unsigned mg = __shfl_sync(FULL, acc, g);   // uniform
            const float gmv = gm[(g << 5) + lane];
            float v;
            if (mg == FULL) {
                v = gmv;                        // whole group visible
            } else if (mg == 0u) {
                v = gmv + NEG_INF;              // whole group masked (exact)
            } else {
                v = -INFINITY;                  // mixed group: per-element
                for (int jj = 0; jj < 32; ++jj) {
                    float fv = fb[(size_t)((g << 5) + jj) * DD + lane];
                    v = fmaxf(v, fv + (((mg >> jj) & 1u) ? 0.0f : NEG_INF));
                }
            }
            best = fmaxf(best, v);
        }
    }
    out[((size_t)b * NN + i) * DD + lane] = best;   // coalesced 128B/warp
}

// ---------------------------------------------------------------------------
extern "C" void kernel_launch(void* const* d_in, const int* in_sizes, int n_in,
                              void* d_out, int out_size) {
    const float* feat;
    const int*   edges;
    if (in_sizes[0] == BATCH * NN * DD) {
        feat  = (const float*)d_in[0];
        edges = (const int*)d_in[1];
    } else {
        feat  = (const float*)d_in[1];
        edges = (const int*)d_in[0];
    }

    pack_gmax_kernel<<<PACK_BLOCKS + GMAX_BLOCKS, 256>>>(edges, feat);
    pool_kernel<<<dim3(NN / 8, BATCH), 256>>>(feat, (float*)d_out);

    (void)n_in; (void)out_size;
}